// round 2
// baseline (speedup 1.0000x reference)
#include <cuda_runtime.h>
#include <cstdint>

#define N_NODES 40000
#define N_EDGES 640000
#define D 128

// ---------------- scratch (device globals: no allocations allowed) ----------
static __device__ float g_H1 [N_NODES * D];   // hidden of message MLP / reused for U2
static __device__ float g_Y  [N_NODES * D];   // per-node message output
static __device__ float g_AGG[N_NODES * D];   // scatter accumulator
static __device__ float g_U1 [N_NODES * D];   // hidden of update MLP
static __device__ float g_CNT[N_NODES];       // in-degree counts
static __device__ int   g_is64;               // edge_index dtype flag

// ---------------- packed fp32x2 FMA (Blackwell FFMA2) -----------------------
__device__ __forceinline__ void fma2(unsigned long long& acc,
                                     unsigned long long a, unsigned long long b) {
    asm("fma.rn.f32x2 %0, %1, %2, %0;" : "+l"(acc) : "l"(a), "l"(b));
}

// ---------------- GEMM: C[M x 128] = act(concat(A0,A1) @ W^T + bias) --------
// A0/A1 are [M x 128] fp32 row-major (A1 used for the K=256 concat case).
// W is [128 x KT] row-major. Tile: 64 rows x 128 cols per block, 256 threads.
// K packed in pairs -> fma.rn.f32x2 with even/odd-k partial sums, recombined
// in the epilogue. SMEM strides 132 / 130 chosen for conflict-free LDS.64.
template <int KT, bool RELU>
__global__ __launch_bounds__(256, 2)
void gemm_kernel(const float* __restrict__ A0, const float* __restrict__ A1,
                 const float* __restrict__ W,  const float* __restrict__ bias,
                 float* __restrict__ C)
{
    extern __shared__ float sm[];
    float* sA = sm;               // [64][132]
    float* sW = sm + 64 * 132;    // [128][130]

    const int tid  = threadIdx.x;
    const int lane = tid & 31;
    const int wrp  = tid >> 5;           // 0..7 : row group
    const int m0   = blockIdx.x * 64;

    unsigned long long acc[8][4];
    #pragma unroll
    for (int i = 0; i < 8; i++) {
        #pragma unroll
        for (int j = 0; j < 4; j++) acc[i][j] = 0ull;
    }

    for (int kc = 0; kc < KT; kc += 128) {
        const float* Asrc = (kc == 0) ? A0 : A1;

        // load A tile: 64 rows x 128 cols, coalesced, STS.128 conflict-free
        #pragma unroll
        for (int rr = wrp; rr < 64; rr += 8) {
            float4 v = *reinterpret_cast<const float4*>(
                Asrc + (size_t)(m0 + rr) * D + lane * 4);
            *reinterpret_cast<float4*>(sA + rr * 132 + lane * 4) = v;
        }
        // load W tile: 128 out-cols x 128 k, store as float2 pairs
        #pragma unroll
        for (int wr = wrp; wr < 128; wr += 8) {
            float4 v = *reinterpret_cast<const float4*>(
                W + (size_t)wr * KT + kc + lane * 4);
            *reinterpret_cast<float2*>(sW + wr * 130 + lane * 4)     = make_float2(v.x, v.y);
            *reinterpret_cast<float2*>(sW + wr * 130 + lane * 4 + 2) = make_float2(v.z, v.w);
        }
        __syncthreads();

        #pragma unroll 4
        for (int k = 0; k < 128; k += 2) {
            unsigned long long a2[8], w2[4];
            #pragma unroll
            for (int i = 0; i < 8; i++)
                a2[i] = *reinterpret_cast<const unsigned long long*>(
                    sA + (wrp * 8 + i) * 132 + k);          // warp-broadcast
            #pragma unroll
            for (int j = 0; j < 4; j++)
                w2[j] = *reinterpret_cast<const unsigned long long*>(
                    sW + (lane + 32 * j) * 130 + k);        // conflict-free
            #pragma unroll
            for (int i = 0; i < 8; i++) {
                #pragma unroll
                for (int j = 0; j < 4; j++)
                    fma2(acc[i][j], a2[i], w2[j]);
            }
        }
        __syncthreads();
    }

    // epilogue: recombine even/odd-k halves, bias, relu, store
    #pragma unroll
    for (int i = 0; i < 8; i++) {
        const int m = m0 + wrp * 8 + i;
        #pragma unroll
        for (int j = 0; j < 4; j++) {
            float2 p = *reinterpret_cast<float2*>(&acc[i][j]);
            float v = p.x + p.y + bias[lane + 32 * j];
            if (RELU) v = fmaxf(v, 0.0f);
            C[(size_t)m * D + lane + 32 * j] = v;
        }
    }
}

// ---------------- helpers ---------------------------------------------------
__global__ void zero_kernel(float* __restrict__ AGG, float* __restrict__ CNT) {
    int i = blockIdx.x * blockDim.x + threadIdx.x;    // 5000*256 = N*32 exactly
    reinterpret_cast<float4*>(AGG)[i] = make_float4(0.f, 0.f, 0.f, 0.f);
    if (i < N_NODES) CNT[i] = 0.f;
}

// edge_index dtype sniff: int64 values < 2^31 viewed as int32 have every odd
// slot == 0 (little-endian high words). Real int32 indices are ~never all 0.
__global__ void detect_kernel(const int* __restrict__ e) {
    if (threadIdx.x == 0) {
        int any = 0;
        for (int i = 1; i < 256; i += 2) any |= e[i];
        g_is64 = (any == 0) ? 1 : 0;
    }
}

// one warp per edge: read Y[src] (float4/lane), vector-atomic into AGG[dst]
__global__ void scatter_kernel(const float* __restrict__ Y,
                               const void* __restrict__ eidx,
                               float* __restrict__ AGG, float* __restrict__ CNT)
{
    const int e    = blockIdx.x * 8 + (threadIdx.x >> 5);
    const int lane = threadIdx.x & 31;
    int src, dst;
    if (g_is64) {
        const long long* p = reinterpret_cast<const long long*>(eidx);
        src = (int)p[e]; dst = (int)p[N_EDGES + e];
    } else {
        const int* p = reinterpret_cast<const int*>(eidx);
        src = p[e]; dst = p[N_EDGES + e];
    }
    float4 v = reinterpret_cast<const float4*>(Y + (size_t)src * D)[lane];
#if defined(__CUDA_ARCH__) && (__CUDA_ARCH__ >= 900)
    atomicAdd(reinterpret_cast<float4*>(AGG + (size_t)dst * D) + lane, v);
#else
    float* a = AGG + (size_t)dst * D + lane * 4;
    atomicAdd(a + 0, v.x); atomicAdd(a + 1, v.y);
    atomicAdd(a + 2, v.z); atomicAdd(a + 3, v.w);
#endif
    if (lane == 0) atomicAdd(CNT + dst, 1.0f);
}

__global__ void normalize_kernel(float* __restrict__ AGG, const float* __restrict__ CNT) {
    int i = blockIdx.x * blockDim.x + threadIdx.x;    // N*32 threads
    int row = i >> 5;
    float s = 1.0f / fmaxf(CNT[row], 1.0f);
    float4 v = reinterpret_cast<float4*>(AGG)[i];
    v.x *= s; v.y *= s; v.z *= s; v.w *= s;
    reinterpret_cast<float4*>(AGG)[i] = v;
}

// residual + LayerNorm, one warp per row, two-pass (mean, then centered var)
__global__ void ln_kernel(const float* __restrict__ U, const float* __restrict__ X,
                          const float* __restrict__ gamma, const float* __restrict__ beta,
                          float* __restrict__ out)
{
    const int r    = blockIdx.x * 8 + (threadIdx.x >> 5);
    const int lane = threadIdx.x & 31;
    float4 u  = reinterpret_cast<const float4*>(U + (size_t)r * D)[lane];
    float4 xv = reinterpret_cast<const float4*>(X + (size_t)r * D)[lane];
    float4 h = make_float4(u.x + xv.x, u.y + xv.y, u.z + xv.z, u.w + xv.w);

    float s = h.x + h.y + h.z + h.w;
    #pragma unroll
    for (int o = 16; o; o >>= 1) s += __shfl_xor_sync(0xffffffffu, s, o);
    const float mu = s * (1.0f / 128.0f);

    float4 d = make_float4(h.x - mu, h.y - mu, h.z - mu, h.w - mu);
    float ss = d.x * d.x + d.y * d.y + d.z * d.z + d.w * d.w;
    #pragma unroll
    for (int o = 16; o; o >>= 1) ss += __shfl_xor_sync(0xffffffffu, ss, o);
    const float rstd = rsqrtf(ss * (1.0f / 128.0f) + 1e-5f);

    float4 g = reinterpret_cast<const float4*>(gamma)[lane];
    float4 b = reinterpret_cast<const float4*>(beta)[lane];
    float4 o4 = make_float4(d.x * rstd * g.x + b.x, d.y * rstd * g.y + b.y,
                            d.z * rstd * g.z + b.z, d.w * rstd * g.w + b.w);
    reinterpret_cast<float4*>(out + (size_t)r * D)[lane] = o4;
}

// ---------------- launch -----------------------------------------------------
extern "C" void kernel_launch(void* const* d_in, const int* in_sizes, int n_in,
                              void* d_out, int out_size)
{
    const float* x     = (const float*)d_in[0];
    const void*  eidx  =               d_in[1];
    const float* Wm1   = (const float*)d_in[2];
    const float* bm1   = (const float*)d_in[3];
    const float* Wm2   = (const float*)d_in[4];
    const float* bm2   = (const float*)d_in[5];
    const float* Wu1   = (const float*)d_in[6];
    const float* bu1   = (const float*)d_in[7];
    const float* Wu2   = (const float*)d_in[8];
    const float* bu2   = (const float*)d_in[9];
    const float* gamma = (const float*)d_in[10];
    const float* beta  = (const float*)d_in[11];
    float* out = (float*)d_out;

    void *pH1, *pY, *pAGG, *pU1, *pCNT;
    cudaGetSymbolAddress(&pH1,  g_H1);
    cudaGetSymbolAddress(&pY,   g_Y);
    cudaGetSymbolAddress(&pAGG, g_AGG);
    cudaGetSymbolAddress(&pU1,  g_U1);
    cudaGetSymbolAddress(&pCNT, g_CNT);

    const int SMEMB = (64 * 132 + 128 * 130) * 4;   // 100352 B
    cudaFuncSetAttribute(gemm_kernel<128, true >, cudaFuncAttributeMaxDynamicSharedMemorySize, SMEMB);
    cudaFuncSetAttribute(gemm_kernel<128, false>, cudaFuncAttributeMaxDynamicSharedMemorySize, SMEMB);
    cudaFuncSetAttribute(gemm_kernel<256, true >, cudaFuncAttributeMaxDynamicSharedMemorySize, SMEMB);

    const int GEMM_GRID = N_NODES / 64;   // 625

    zero_kernel  <<<5000, 256>>>((float*)pAGG, (float*)pCNT);
    detect_kernel<<<1, 32>>>((const int*)eidx);

    // message MLP per NODE (algebraically identical to per-edge)
    gemm_kernel<128, true ><<<GEMM_GRID, 256, SMEMB>>>(x, nullptr, Wm1, bm1, (float*)pH1);
    gemm_kernel<128, false><<<GEMM_GRID, 256, SMEMB>>>((const float*)pH1, nullptr, Wm2, bm2, (float*)pY);

    // scatter-mean
    scatter_kernel  <<<N_EDGES / 8, 256>>>((const float*)pY, eidx, (float*)pAGG, (float*)pCNT);
    normalize_kernel<<<5000, 256>>>((float*)pAGG, (const float*)pCNT);

    // update MLP on concat([x, agg])
    gemm_kernel<256, true ><<<GEMM_GRID, 256, SMEMB>>>(x, (const float*)pAGG, Wu1, bu1, (float*)pU1);
    gemm_kernel<128, false><<<GEMM_GRID, 256, SMEMB>>>((const float*)pU1, nullptr, Wu2, bu2, (float*)pH1);

    // residual + LayerNorm
    ln_kernel<<<5000, 256>>>((const float*)pH1, x, gamma, beta, out);
}

// round 8
// speedup vs baseline: 1.5406x; 1.5406x over previous
#include <cuda_runtime.h>
#include <cuda_bf16.h>
#include <cstdint>

#define N_NODES 40000
#define N_EDGES 640000
#define D 128

// ---------------- scratch (device globals: no allocations allowed) ----------
static __device__ float g_H1 [N_NODES * D];   // hidden of message MLP / reused for U2
static __device__ float g_Y  [N_NODES * D];   // per-node message output
static __device__ float g_AGG[N_NODES * D];   // scatter accumulator
static __device__ float g_U1 [N_NODES * D];   // hidden of update MLP
static __device__ float g_CNT[N_NODES];       // in-degree counts
static __device__ int   g_is64;               // edge_index dtype flag
// pre-split weights (bf16 hi / lo), [n][k] row-major:
//   Wm1 @ 0 (16384), Wm2 @ 16384, Wu1 @ 32768 (32768), Wu2 @ 65536
static __device__ unsigned short g_Wh[81920];
static __device__ unsigned short g_Wl[81920];

// ---------------- helpers ----------------------------------------------------
__device__ __forceinline__ uint32_t smem_u32(const void* p) {
    return (uint32_t)__cvta_generic_to_shared(p);
}

// split 4 fp32 -> bf16 hi (truncate) pairs + bf16 lo (rn of residual) pairs
__device__ __forceinline__ void split4(float4 v, uint32_t& h01, uint32_t& h23,
                                       uint32_t& l01, uint32_t& l23) {
    uint32_t u0 = __float_as_uint(v.x), u1 = __float_as_uint(v.y);
    uint32_t u2 = __float_as_uint(v.z), u3 = __float_as_uint(v.w);
    asm("prmt.b32 %0, %1, %2, 0x7632;" : "=r"(h01) : "r"(u0), "r"(u1));
    asm("prmt.b32 %0, %1, %2, 0x7632;" : "=r"(h23) : "r"(u2), "r"(u3));
    float lo0 = v.x - __uint_as_float(u0 & 0xFFFF0000u);
    float lo1 = v.y - __uint_as_float(u1 & 0xFFFF0000u);
    float lo2 = v.z - __uint_as_float(u2 & 0xFFFF0000u);
    float lo3 = v.w - __uint_as_float(u3 & 0xFFFF0000u);
    asm("cvt.rn.bf16x2.f32 %0, %1, %2;" : "=r"(l01) : "f"(lo1), "f"(lo0));
    asm("cvt.rn.bf16x2.f32 %0, %1, %2;" : "=r"(l23) : "f"(lo3), "f"(lo2));
}

#define LDSM_X4(r0, r1, r2, r3, addr) \
    asm volatile("ldmatrix.sync.aligned.m8n8.x4.shared.b16 {%0,%1,%2,%3}, [%4];" \
        : "=r"(r0), "=r"(r1), "=r"(r2), "=r"(r3) : "r"(addr))

#define MMA_BF16(c, a, b) \
    asm volatile("mma.sync.aligned.m16n8k16.row.col.f32.bf16.bf16.f32 " \
        "{%0,%1,%2,%3}, {%4,%5,%6,%7}, {%8,%9}, {%0,%1,%2,%3};" \
        : "+f"((c)[0]), "+f"((c)[1]), "+f"((c)[2]), "+f"((c)[3]) \
        : "r"((a)[0]), "r"((a)[1]), "r"((a)[2]), "r"((a)[3]), \
          "r"((b)[0]), "r"((b)[1]))

// ---------------- tensor-core GEMM: C = act(concat(A0,A1) @ W^T + bias) -----
// fp32 in/out. A split to bf16 hi/lo in-kernel; W pre-split in g_Wh/g_Wl.
// 3-pass mma (hi*hi + hi*lo + lo*hi), error ~2^-16.
// Block: 256 thr (8 warps, 2x4 grid), tile M=64 x N=128, K-chunk 128.
// Warp tile 32x32 (2 m16-tiles x 4 n8-tiles).
template <int KT, bool RELU>
__global__ __launch_bounds__(256, 2)
void gemm_ts(const float* __restrict__ A0, const float* __restrict__ A1,
             int woff, const float* __restrict__ bias, float* __restrict__ C)
{
    extern __shared__ char smc[];
    float* sbias = (float*)smc;                               // 512 B
    unsigned short* sAhi = (unsigned short*)(smc + 512);      // [64][136]
    unsigned short* sAlo = sAhi + 64 * 136;
    unsigned short* sBhi = sAlo + 64 * 136;                   // [128][136]
    unsigned short* sBlo = sBhi + 128 * 136;

    const int tid  = threadIdx.x;
    const int lane = tid & 31;
    const int wid  = tid >> 5;
    const int wm   = (wid >> 2) * 32;        // warp m offset (0 / 32)
    const int wn   = (wid & 3) * 32;         // warp n offset (0/32/64/96)
    const int m0   = blockIdx.x * 64;

    if (tid < 128) sbias[tid] = bias[tid];

    float c[2][4][4];
    #pragma unroll
    for (int i = 0; i < 2; i++)
        #pragma unroll
        for (int j = 0; j < 4; j++)
            #pragma unroll
            for (int q = 0; q < 4; q++) c[i][j][q] = 0.0f;

    // per-lane ldmatrix row/khalf decomposition
    const int a_row = lane & 15, a_kh = (lane >> 4) * 8;           // A x4
    const int b_row = (lane >> 4) * 8 + (lane & 7);                // B x4
    const int b_kh  = ((lane >> 3) & 1) * 8;

    const int nchunks = KT / 128;
    for (int kc = 0; kc < nchunks; ++kc) {
        const float* Asrc = (kc == 0) ? A0 : A1;
        __syncthreads();

        // fill A tile: 64x128 fp32 -> hi/lo bf16 (2048 float4, 8 iters)
        #pragma unroll
        for (int it = 0; it < 8; ++it) {
            int idx  = tid + it * 256;
            int row  = idx >> 5;             // /32 float4 per row
            int col4 = idx & 31;
            float4 v = *reinterpret_cast<const float4*>(
                Asrc + (size_t)(m0 + row) * D + col4 * 4);
            uint32_t h01, h23, l01, l23;
            split4(v, h01, h23, l01, l23);
            *reinterpret_cast<uint2*>(sAhi + row * 136 + col4 * 4) = make_uint2(h01, h23);
            *reinterpret_cast<uint2*>(sAlo + row * 136 + col4 * 4) = make_uint2(l01, l23);
        }
        // fill B tiles: copy pre-split bf16 (128x128, 2048 uint4 each)
        #pragma unroll
        for (int it = 0; it < 8; ++it) {
            int idx = tid + it * 256;
            int row = idx >> 4;              // /16 uint4 per row
            int c8  = idx & 15;
            size_t gsrc = (size_t)woff + (size_t)row * KT + kc * 128 + c8 * 8;
            *reinterpret_cast<uint4*>(sBhi + row * 136 + c8 * 8) =
                *reinterpret_cast<const uint4*>(g_Wh + gsrc);
            *reinterpret_cast<uint4*>(sBlo + row * 136 + c8 * 8) =
                *reinterpret_cast<const uint4*>(g_Wl + gsrc);
        }
        __syncthreads();

        #pragma unroll
        for (int ks = 0; ks < 8; ++ks) {
            const int kb = ks * 16;
            uint32_t ah[2][4], al[2][4], bh[4][2], bl[4][2];
            #pragma unroll
            for (int mt = 0; mt < 2; ++mt) {
                uint32_t addr = smem_u32(sAhi + (wm + mt * 16 + a_row) * 136 + kb + a_kh);
                LDSM_X4(ah[mt][0], ah[mt][1], ah[mt][2], ah[mt][3], addr);
                addr = smem_u32(sAlo + (wm + mt * 16 + a_row) * 136 + kb + a_kh);
                LDSM_X4(al[mt][0], al[mt][1], al[mt][2], al[mt][3], addr);
            }
            #pragma unroll
            for (int bt = 0; bt < 2; ++bt) {   // each x4 covers 2 n8-tiles
                uint32_t addr = smem_u32(sBhi + (wn + bt * 16 + b_row) * 136 + kb + b_kh);
                LDSM_X4(bh[bt*2][0], bh[bt*2][1], bh[bt*2+1][0], bh[bt*2+1][1], addr);
                addr = smem_u32(sBlo + (wn + bt * 16 + b_row) * 136 + kb + b_kh);
                LDSM_X4(bl[bt*2][0], bl[bt*2][1], bl[bt*2+1][0], bl[bt*2+1][1], addr);
            }
            #pragma unroll
            for (int mt = 0; mt < 2; ++mt) {
                #pragma unroll
                for (int nt = 0; nt < 4; ++nt) {
                    MMA_BF16(c[mt][nt], ah[mt], bh[nt]);   // hi*hi
                    MMA_BF16(c[mt][nt], ah[mt], bl[nt]);   // hi*lo
                    MMA_BF16(c[mt][nt], al[mt], bh[nt]);   // lo*hi
                }
            }
        }
    }

    // epilogue: c0,c1 = (row g, col 2t,2t+1); c2,c3 = row g+8
    const int g  = lane >> 2;
    const int cl = (lane & 3) * 2;
    #pragma unroll
    for (int mt = 0; mt < 2; ++mt) {
        const int m = m0 + wm + mt * 16 + g;
        #pragma unroll
        for (int nt = 0; nt < 4; ++nt) {
            const int n = wn + nt * 8 + cl;
            float2 o0, o1;
            o0.x = c[mt][nt][0] + sbias[n];
            o0.y = c[mt][nt][1] + sbias[n + 1];
            o1.x = c[mt][nt][2] + sbias[n];
            o1.y = c[mt][nt][3] + sbias[n + 1];
            if (RELU) {
                o0.x = fmaxf(o0.x, 0.f); o0.y = fmaxf(o0.y, 0.f);
                o1.x = fmaxf(o1.x, 0.f); o1.y = fmaxf(o1.y, 0.f);
            }
            *reinterpret_cast<float2*>(C + (size_t)m * D + n)       = o0;
            *reinterpret_cast<float2*>(C + (size_t)(m + 8) * D + n) = o1;
        }
    }
}

// ---------------- weight pre-split -------------------------------------------
__global__ void wsplit_kernel(const float* __restrict__ Wm1, const float* __restrict__ Wm2,
                              const float* __restrict__ Wu1, const float* __restrict__ Wu2)
{
    int i = blockIdx.x * blockDim.x + threadIdx.x;
    if (i >= 81920) return;
    float f;
    if      (i < 16384) f = Wm1[i];
    else if (i < 32768) f = Wm2[i - 16384];
    else if (i < 65536) f = Wu1[i - 32768];
    else                f = Wu2[i - 65536];
    uint32_t u = __float_as_uint(f);
    g_Wh[i] = (unsigned short)(u >> 16);                     // truncate
    float lo = f - __uint_as_float(u & 0xFFFF0000u);
    g_Wl[i] = __bfloat16_as_ushort(__float2bfloat16(lo));    // rn residual
}

// ---------------- helpers ---------------------------------------------------
__global__ void zero_kernel(float* __restrict__ AGG, float* __restrict__ CNT) {
    int i = blockIdx.x * blockDim.x + threadIdx.x;    // 5000*256 = N*32 exactly
    reinterpret_cast<float4*>(AGG)[i] = make_float4(0.f, 0.f, 0.f, 0.f);
    if (i < N_NODES) CNT[i] = 0.f;
}

// edge_index dtype sniff: int64 values < 2^31 viewed as int32 have every odd
// slot == 0 (little-endian high words). Real int32 indices are ~never all 0.
__global__ void detect_kernel(const int* __restrict__ e) {
    if (threadIdx.x == 0) {
        int any = 0;
        for (int i = 1; i < 256; i += 2) any |= e[i];
        g_is64 = (any == 0) ? 1 : 0;
    }
}

// one warp per edge: read Y[src] (float4/lane), vector-atomic into AGG[dst]
__global__ void scatter_kernel(const float* __restrict__ Y,
                               const void* __restrict__ eidx,
                               float* __restrict__ AGG, float* __restrict__ CNT)
{
    const int e    = blockIdx.x * 8 + (threadIdx.x >> 5);
    const int lane = threadIdx.x & 31;
    int src, dst;
    if (g_is64) {
        const long long* p = reinterpret_cast<const long long*>(eidx);
        src = (int)p[e]; dst = (int)p[N_EDGES + e];
    } else {
        const int* p = reinterpret_cast<const int*>(eidx);
        src = p[e]; dst = p[N_EDGES + e];
    }
    float4 v = reinterpret_cast<const float4*>(Y + (size_t)src * D)[lane];
#if defined(__CUDA_ARCH__) && (__CUDA_ARCH__ >= 900)
    atomicAdd(reinterpret_cast<float4*>(AGG + (size_t)dst * D) + lane, v);
#else
    float* a = AGG + (size_t)dst * D + lane * 4;
    atomicAdd(a + 0, v.x); atomicAdd(a + 1, v.y);
    atomicAdd(a + 2, v.z); atomicAdd(a + 3, v.w);
#endif
    if (lane == 0) atomicAdd(CNT + dst, 1.0f);
}

__global__ void normalize_kernel(float* __restrict__ AGG, const float* __restrict__ CNT) {
    int i = blockIdx.x * blockDim.x + threadIdx.x;    // N*32 threads
    int row = i >> 5;
    float s = 1.0f / fmaxf(CNT[row], 1.0f);
    float4 v = reinterpret_cast<float4*>(AGG)[i];
    v.x *= s; v.y *= s; v.z *= s; v.w *= s;
    reinterpret_cast<float4*>(AGG)[i] = v;
}

// residual + LayerNorm, one warp per row
__global__ void ln_kernel(const float* __restrict__ U, const float* __restrict__ X,
                          const float* __restrict__ gamma, const float* __restrict__ beta,
                          float* __restrict__ out)
{
    const int r    = blockIdx.x * 8 + (threadIdx.x >> 5);
    const int lane = threadIdx.x & 31;
    float4 u  = reinterpret_cast<const float4*>(U + (size_t)r * D)[lane];
    float4 xv = reinterpret_cast<const float4*>(X + (size_t)r * D)[lane];
    float4 h = make_float4(u.x + xv.x, u.y + xv.y, u.z + xv.z, u.w + xv.w);

    float s = h.x + h.y + h.z + h.w;
    #pragma unroll
    for (int o = 16; o; o >>= 1) s += __shfl_xor_sync(0xffffffffu, s, o);
    const float mu = s * (1.0f / 128.0f);

    float4 d = make_float4(h.x - mu, h.y - mu, h.z - mu, h.w - mu);
    float ss = d.x * d.x + d.y * d.y + d.z * d.z + d.w * d.w;
    #pragma unroll
    for (int o = 16; o; o >>= 1) ss += __shfl_xor_sync(0xffffffffu, ss, o);
    const float rstd = rsqrtf(ss * (1.0f / 128.0f) + 1e-5f);

    float4 g = reinterpret_cast<const float4*>(gamma)[lane];
    float4 b = reinterpret_cast<const float4*>(beta)[lane];
    float4 o4 = make_float4(d.x * rstd * g.x + b.x, d.y * rstd * g.y + b.y,
                            d.z * rstd * g.z + b.z, d.w * rstd * g.w + b.w);
    reinterpret_cast<float4*>(out + (size_t)r * D)[lane] = o4;
}

// ---------------- launch -----------------------------------------------------
extern "C" void kernel_launch(void* const* d_in, const int* in_sizes, int n_in,
                              void* d_out, int out_size)
{
    const float* x     = (const float*)d_in[0];
    const void*  eidx  =               d_in[1];
    const float* Wm1   = (const float*)d_in[2];
    const float* bm1   = (const float*)d_in[3];
    const float* Wm2   = (const float*)d_in[4];
    const float* bm2   = (const float*)d_in[5];
    const float* Wu1   = (const float*)d_in[6];
    const float* bu1   = (const float*)d_in[7];
    const float* Wu2   = (const float*)d_in[8];
    const float* bu2   = (const float*)d_in[9];
    const float* gamma = (const float*)d_in[10];
    const float* beta  = (const float*)d_in[11];
    float* out = (float*)d_out;

    void *pH1, *pY, *pAGG, *pU1, *pCNT;
    cudaGetSymbolAddress(&pH1,  g_H1);
    cudaGetSymbolAddress(&pY,   g_Y);
    cudaGetSymbolAddress(&pAGG, g_AGG);
    cudaGetSymbolAddress(&pU1,  g_U1);
    cudaGetSymbolAddress(&pCNT, g_CNT);

    // smem: 512 bias + (64+64)*136*2 (A hi/lo) + (128+128)*136*2 (B hi/lo)
    const int SMEMB = 512 + 2 * (64 * 136 * 2) + 2 * (128 * 136 * 2);  // 104960
    cudaFuncSetAttribute(gemm_ts<128, true >, cudaFuncAttributeMaxDynamicSharedMemorySize, SMEMB);
    cudaFuncSetAttribute(gemm_ts<128, false>, cudaFuncAttributeMaxDynamicSharedMemorySize, SMEMB);
    cudaFuncSetAttribute(gemm_ts<256, true >, cudaFuncAttributeMaxDynamicSharedMemorySize, SMEMB);

    const int GEMM_GRID = N_NODES / 64;   // 625, exact

    zero_kernel  <<<5000, 256>>>((float*)pAGG, (float*)pCNT);
    detect_kernel<<<1, 32>>>((const int*)eidx);
    wsplit_kernel<<<(81920 + 255) / 256, 256>>>(Wm1, Wm2, Wu1, Wu2);

    // message MLP per NODE (algebraically identical to per-edge)
    gemm_ts<128, true ><<<GEMM_GRID, 256, SMEMB>>>(x, nullptr, 0,     bm1, (float*)pH1);
    gemm_ts<128, false><<<GEMM_GRID, 256, SMEMB>>>((const float*)pH1, nullptr, 16384, bm2, (float*)pY);

    // scatter-mean
    scatter_kernel  <<<N_EDGES / 8, 256>>>((const float*)pY, eidx, (float*)pAGG, (float*)pCNT);
    normalize_kernel<<<5000, 256>>>((float*)pAGG, (const float*)pCNT);

    // update MLP on concat([x, agg])
    gemm_ts<256, true ><<<GEMM_GRID, 256, SMEMB>>>(x, (const float*)pAGG, 32768, bu1, (float*)pU1);
    gemm_ts<128, false><<<GEMM_GRID, 256, SMEMB>>>((const float*)pU1, nullptr, 65536, bu2, (float*)pH1);

    // residual + LayerNorm
    ln_kernel<<<5000, 256>>>((const float*)pH1, x, gamma, beta, out);
}